// round 1
// baseline (speedup 1.0000x reference)
#include <cuda_runtime.h>
#include <math.h>

#define BATCH 16
#define SEQ   1024
#define DMODEL 512
#define NHEAD 8
#define HD    64
#define MROWS (BATCH * SEQ)   // 16384

// Scratch: projected Q/K/V and attention output, laid out (b, n, h, e) so that
// flattening (h,e) matches the reference's concat layout.
__device__ float g_q[(size_t)MROWS * DMODEL];
__device__ float g_k[(size_t)MROWS * DMODEL];
__device__ float g_v[(size_t)MROWS * DMODEL];
__device__ float g_o[(size_t)MROWS * DMODEL];

// C[M,512] = A[M,512] @ W[512,512]^T   (both row-major; classic NT sgemm)
// 128x128 tile, BK=16, 256 threads, 8x8 per-thread microtile.
__global__ __launch_bounds__(256) void gemm_nt(const float* __restrict__ A,
                                               const float* __restrict__ W,
                                               float* __restrict__ C) {
    const int K = 512;
    __shared__ float As[16][132];
    __shared__ float Ws[16][132];
    const int bm = blockIdx.y * 128;
    const int bn = blockIdx.x * 128;
    const int tid = threadIdx.x;
    const int tx = tid & 15, ty = tid >> 4;
    float acc[8][8] = {};
    for (int k0 = 0; k0 < K; k0 += 16) {
#pragma unroll
        for (int l = 0; l < 2; l++) {
            int idx = tid + l * 256;          // 0..511
            int row = idx >> 2;               // 0..127
            int kc  = (idx & 3) << 2;         // 0,4,8,12
            float4 va = *(const float4*)(A + (size_t)(bm + row) * K + k0 + kc);
            As[kc + 0][row] = va.x; As[kc + 1][row] = va.y;
            As[kc + 2][row] = va.z; As[kc + 3][row] = va.w;
            float4 vw = *(const float4*)(W + (size_t)(bn + row) * K + k0 + kc);
            Ws[kc + 0][row] = vw.x; Ws[kc + 1][row] = vw.y;
            Ws[kc + 2][row] = vw.z; Ws[kc + 3][row] = vw.w;
        }
        __syncthreads();
#pragma unroll
        for (int k = 0; k < 16; k++) {
            float a[8], b[8];
            *(float4*)&a[0] = *(const float4*)&As[k][ty * 8];
            *(float4*)&a[4] = *(const float4*)&As[k][ty * 8 + 4];
            *(float4*)&b[0] = *(const float4*)&Ws[k][tx * 8];
            *(float4*)&b[4] = *(const float4*)&Ws[k][tx * 8 + 4];
#pragma unroll
            for (int i = 0; i < 8; i++)
#pragma unroll
                for (int j = 0; j < 8; j++)
                    acc[i][j] = fmaf(a[i], b[j], acc[i][j]);
        }
        __syncthreads();
    }
#pragma unroll
    for (int i = 0; i < 8; i++) {
        float* cp = C + (size_t)(bm + ty * 8 + i) * 512 + bn + tx * 8;
        *(float4*)cp       = make_float4(acc[i][0], acc[i][1], acc[i][2], acc[i][3]);
        *(float4*)(cp + 4) = make_float4(acc[i][4], acc[i][5], acc[i][6], acc[i][7]);
    }
}

// Flash attention, one (b,h) per blockIdx.y, 64 queries per block, 64-wide KV tiles.
// Q/K/V/O layout: (b, n, h, e) i.e. per-(b,h) base = b*SEQ*DMODEL + h*HD, row stride DMODEL.
// Dynamic smem: Qs[64][65] Ks[64][65] Vs[64][65] Ps[64][65] = 66560 B.
__global__ __launch_bounds__(256) void flash_attn(const float* __restrict__ Qg,
                                                  const float* __restrict__ Kg,
                                                  const float* __restrict__ Vg,
                                                  float* __restrict__ Og) {
    extern __shared__ float sm[];
    float (*Qs)[65] = (float(*)[65])(sm);
    float (*Ks)[65] = (float(*)[65])(sm + 64 * 65);
    float (*Vs)[65] = (float(*)[65])(sm + 2 * 64 * 65);
    float (*Ps)[65] = (float(*)[65])(sm + 3 * 64 * 65);

    const int qb = blockIdx.x;            // 0..15 (query tile)
    const int bh = blockIdx.y;            // 0..127
    const int b = bh >> 3, h = bh & 7;
    const size_t base = (size_t)b * SEQ * DMODEL + (size_t)h * HD;
    const int tid = threadIdx.x;
    const int tx = tid & 15, ty = tid >> 4;

    // Load Q tile, pre-scaled by 1/sqrt(HD) = 1/8
#pragma unroll
    for (int l = 0; l < 4; l++) {
        int idx = tid + l * 256;          // 0..1023
        int row = idx >> 4;
        int col = (idx & 15) << 2;
        float4 v = *(const float4*)(Qg + base + (size_t)(qb * 64 + row) * DMODEL + col);
        Qs[row][col]     = v.x * 0.125f;
        Qs[row][col + 1] = v.y * 0.125f;
        Qs[row][col + 2] = v.z * 0.125f;
        Qs[row][col + 3] = v.w * 0.125f;
    }

    float m_i[4], l_i[4], acc[4][4];
#pragma unroll
    for (int r = 0; r < 4; r++) {
        m_i[r] = -1e30f;
        l_i[r] = 0.f;
#pragma unroll
        for (int c = 0; c < 4; c++) acc[r][c] = 0.f;
    }

    for (int kt = 0; kt < SEQ / 64; kt++) {
        // Load K and V tiles
#pragma unroll
        for (int l = 0; l < 4; l++) {
            int idx = tid + l * 256;
            int row = idx >> 4;
            int col = (idx & 15) << 2;
            size_t off = base + (size_t)(kt * 64 + row) * DMODEL + col;
            float4 v = *(const float4*)(Kg + off);
            Ks[row][col] = v.x; Ks[row][col + 1] = v.y;
            Ks[row][col + 2] = v.z; Ks[row][col + 3] = v.w;
            float4 w = *(const float4*)(Vg + off);
            Vs[row][col] = w.x; Vs[row][col + 1] = w.y;
            Vs[row][col + 2] = w.z; Vs[row][col + 3] = w.w;
        }
        __syncthreads();   // also covers Qs on first iteration

        // S = Q K^T  (thread owns rows ty*4+r, cols tx*4+c)
        float s[4][4] = {};
#pragma unroll
        for (int k = 0; k < 64; k++) {
            float q[4], kk[4];
#pragma unroll
            for (int r = 0; r < 4; r++) q[r] = Qs[ty * 4 + r][k];
#pragma unroll
            for (int c = 0; c < 4; c++) kk[c] = Ks[tx * 4 + c][k];
#pragma unroll
            for (int r = 0; r < 4; r++)
#pragma unroll
                for (int c = 0; c < 4; c++)
                    s[r][c] = fmaf(q[r], kk[c], s[r][c]);
        }

        // Online softmax: row groups are the 16 tx-lanes of each half-warp
#pragma unroll
        for (int r = 0; r < 4; r++) {
            float mx = fmaxf(fmaxf(s[r][0], s[r][1]), fmaxf(s[r][2], s[r][3]));
#pragma unroll
            for (int off = 8; off >= 1; off >>= 1)
                mx = fmaxf(mx, __shfl_xor_sync(0xffffffffu, mx, off));
            float mnew = fmaxf(m_i[r], mx);
            float corr = __expf(m_i[r] - mnew);
            m_i[r] = mnew;
            l_i[r] *= corr;
#pragma unroll
            for (int c = 0; c < 4; c++) acc[r][c] *= corr;
            float ps = 0.f;
#pragma unroll
            for (int c = 0; c < 4; c++) {
                float p = __expf(s[r][c] - mnew);
                Ps[ty * 4 + r][tx * 4 + c] = p;
                ps += p;
            }
#pragma unroll
            for (int off = 8; off >= 1; off >>= 1)
                ps += __shfl_xor_sync(0xffffffffu, ps, off);
            l_i[r] += ps;
        }
        __syncthreads();   // Ps visible; all Ks reads done

        // O += P @ V  (thread owns rows ty*4+r, HD cols tx*4+c)
#pragma unroll 8
        for (int j = 0; j < 64; j++) {
            float p[4], v[4];
#pragma unroll
            for (int r = 0; r < 4; r++) p[r] = Ps[ty * 4 + r][j];
#pragma unroll
            for (int c = 0; c < 4; c++) v[c] = Vs[j][tx * 4 + c];
#pragma unroll
            for (int r = 0; r < 4; r++)
#pragma unroll
                for (int c = 0; c < 4; c++)
                    acc[r][c] = fmaf(p[r], v[c], acc[r][c]);
        }
        __syncthreads();   // done with Ps/Vs before next tile overwrites
    }

    // Normalize and store O in (b, n, h, e) layout
#pragma unroll
    for (int r = 0; r < 4; r++) {
        float inv = 1.f / l_i[r];
        float4 o = make_float4(acc[r][0] * inv, acc[r][1] * inv,
                               acc[r][2] * inv, acc[r][3] * inv);
        *(float4*)(Og + base + (size_t)(qb * 64 + ty * 4 + r) * DMODEL + tx * 4) = o;
    }
}

extern "C" void kernel_launch(void* const* d_in, const int* in_sizes, int n_in,
                              void* d_out, int out_size) {
    const float* x   = (const float*)d_in[0];
    const float* r   = (const float*)d_in[1];
    const float* x_q = (const float*)d_in[2];
    const float* Wq  = (const float*)d_in[3];   // (H, HD, D) == (512, 512) row-major
    const float* Wk  = (const float*)d_in[4];
    const float* Wv  = (const float*)d_in[5];
    const float* Wo  = (const float*)d_in[6];   // (512, 512)
    float* out = (float*)d_out;

    float *pq, *pk, *pv, *po;
    cudaGetSymbolAddress((void**)&pq, g_q);
    cudaGetSymbolAddress((void**)&pk, g_k);
    cudaGetSymbolAddress((void**)&pv, g_v);
    cudaGetSymbolAddress((void**)&po, g_o);

    const int flash_smem = 4 * 64 * 65 * (int)sizeof(float);  // 66560
    cudaFuncSetAttribute(flash_attn, cudaFuncAttributeMaxDynamicSharedMemorySize,
                         flash_smem);

    dim3 ggrid(4, 128);   // 512 cols / 128, 16384 rows / 128
    // Projections: note V is projected BEFORE attention (valid since Wv is linear:
    // attn @ r @ Wv^T == attn @ (r @ Wv^T)); this removes the 137-GFLOP ctx GEMM.
    gemm_nt<<<ggrid, 256>>>(x_q, Wq, pq);
    gemm_nt<<<ggrid, 256>>>(x,   Wk, pk);
    gemm_nt<<<ggrid, 256>>>(r,   Wv, pv);

    dim3 fgrid(16, 128);  // query tiles x (b,h)
    flash_attn<<<fgrid, 256, flash_smem>>>(pq, pk, pv, po);

    // Output projection: concat(b,n,(h,e)) @ Wo^T
    gemm_nt<<<ggrid, 256>>>(po, Wo, out);
}

// round 2
// speedup vs baseline: 3.4881x; 3.4881x over previous
#include <cuda_runtime.h>
#include <stdint.h>

#define SEQ    1024
#define DM     512
#define HD     64
#define MROWS  16384

// Scratch: projected Q/K/V (layout (b,n,h,e)) and attention output.
__device__ float g_q[MROWS * DM];
__device__ float g_k[MROWS * DM];
__device__ float g_v[MROWS * DM];
__device__ float g_o[MROWS * DM];

// ---------------- PTX helpers ----------------
__device__ __forceinline__ uint32_t f2tf32(float x) {
    uint32_t r;
    asm("cvt.rna.tf32.f32 %0, %1;" : "=r"(r) : "f"(x));
    return r;
}

__device__ __forceinline__ void ldsm4(uint32_t r[4], uint32_t addr) {
    asm volatile("ldmatrix.sync.aligned.m8n8.x4.shared.b16 {%0,%1,%2,%3}, [%4];"
                 : "=r"(r[0]), "=r"(r[1]), "=r"(r[2]), "=r"(r[3])
                 : "r"(addr));
}

__device__ __forceinline__ void mma8(float c[4], const uint32_t a[4],
                                     uint32_t b0, uint32_t b1) {
    asm volatile(
        "mma.sync.aligned.m16n8k8.row.col.f32.tf32.tf32.f32 "
        "{%0,%1,%2,%3},{%4,%5,%6,%7},{%8,%9},{%0,%1,%2,%3};"
        : "+f"(c[0]), "+f"(c[1]), "+f"(c[2]), "+f"(c[3])
        : "r"(a[0]), "r"(a[1]), "r"(a[2]), "r"(a[3]), "r"(b0), "r"(b1));
}

__device__ __forceinline__ void cpasync16(uint32_t dst, const void* src) {
    asm volatile("cp.async.cg.shared.global [%0], [%1], 16;" :: "r"(dst), "l"(src));
}
__device__ __forceinline__ void cpcommit() { asm volatile("cp.async.commit_group;"); }
__device__ __forceinline__ void cpwait0()  { asm volatile("cp.async.wait_group 0;"); }

// ---------------- GEMM: C[M,512] = A[M,512] @ W[512,512]^T (tf32 tensor) --------
// 128x128 block tile, BK=32, 256 threads (8 warps, 4x2), warp tile 32x64.
__global__ __launch_bounds__(256) void gemm_tf32(const float* __restrict__ A,
                                                 const float* __restrict__ W,
                                                 float* __restrict__ C) {
    extern __shared__ char smem[];
    const int tid = threadIdx.x, lane = tid & 31, w = tid >> 5;
    const int bm = blockIdx.y * 128, bn = blockIdx.x * 128;
    const int wm = (w & 3) * 32, wn = (w >> 2) * 64;
    const uint32_t sbase = (uint32_t)__cvta_generic_to_shared(smem);

    const int lr0 = tid >> 3;      // 0..31, +32 per step
    const int lchunk = tid & 7;    // 16B chunk within 128B row

    float acc[2][8][4];
#pragma unroll
    for (int mt = 0; mt < 2; mt++)
#pragma unroll
        for (int nt = 0; nt < 8; nt++)
#pragma unroll
            for (int i = 0; i < 4; i++) acc[mt][nt][i] = 0.f;

    // prologue load tile 0
    {
        uint32_t abuf = sbase, bbuf = sbase + 16384;
#pragma unroll
        for (int l = 0; l < 4; l++) {
            int row = lr0 + l * 32;
            uint32_t dst = row * 128 + ((lchunk * 16) ^ ((row & 7) << 4));
            cpasync16(abuf + dst, A + (size_t)(bm + row) * DM + lchunk * 4);
            cpasync16(bbuf + dst, W + (size_t)(bn + row) * DM + lchunk * 4);
        }
        cpcommit();
    }

    for (int kb = 0; kb < 16; kb++) {
        cpwait0();
        __syncthreads();
        if (kb < 15) {
            uint32_t abuf = sbase + ((kb + 1) & 1) * 32768;
            uint32_t bbuf = abuf + 16384;
#pragma unroll
            for (int l = 0; l < 4; l++) {
                int row = lr0 + l * 32;
                uint32_t dst = row * 128 + ((lchunk * 16) ^ ((row & 7) << 4));
                cpasync16(abuf + dst, A + (size_t)(bm + row) * DM + (kb + 1) * 32 + lchunk * 4);
                cpasync16(bbuf + dst, W + (size_t)(bn + row) * DM + (kb + 1) * 32 + lchunk * 4);
            }
            cpcommit();
        }
        uint32_t abuf = sbase + (kb & 1) * 32768;
        uint32_t bbuf = abuf + 16384;
#pragma unroll
        for (int ks = 0; ks < 4; ks++) {
            uint32_t a[2][4], b[4][4];
#pragma unroll
            for (int mt = 0; mt < 2; mt++) {
                int row = wm + mt * 16 + (lane & 7) + ((lane >> 3) & 1) * 8;
                uint32_t ad = abuf + row * 128 +
                              ((ks * 32 + (lane & 16)) ^ ((row & 7) << 4));
                ldsm4(a[mt], ad);
#pragma unroll
                for (int i = 0; i < 4; i++) a[mt][i] = f2tf32(__uint_as_float(a[mt][i]));
            }
#pragma unroll
            for (int p = 0; p < 4; p++) {
                int row = wn + p * 16 + (lane & 7) + ((lane >> 4) & 1) * 8;
                uint32_t bd = bbuf + row * 128 +
                              ((ks * 32 + ((lane & 8) << 1)) ^ ((row & 7) << 4));
                ldsm4(b[p], bd);
#pragma unroll
                for (int i = 0; i < 4; i++) b[p][i] = f2tf32(__uint_as_float(b[p][i]));
            }
#pragma unroll
            for (int mt = 0; mt < 2; mt++)
#pragma unroll
                for (int nt = 0; nt < 8; nt++)
                    mma8(acc[mt][nt], a[mt], b[nt >> 1][(nt & 1) * 2],
                         b[nt >> 1][(nt & 1) * 2 + 1]);
        }
    }

    // epilogue
#pragma unroll
    for (int mt = 0; mt < 2; mt++)
#pragma unroll
        for (int nt = 0; nt < 8; nt++) {
            int row = bm + wm + mt * 16 + (lane >> 2);
            int col = bn + wn + nt * 8 + (lane & 3) * 2;
            float2 v0 = make_float2(acc[mt][nt][0], acc[mt][nt][1]);
            float2 v1 = make_float2(acc[mt][nt][2], acc[mt][nt][3]);
            *(float2*)(C + (size_t)row * DM + col) = v0;
            *(float2*)(C + (size_t)(row + 8) * DM + col) = v1;
        }
}

// ---------------- Flash attention (tf32 tensor) ----------------
// One (b,h) per blockIdx.y, 128 queries per block, 64-wide KV tiles, 8 warps.
// smem: Qs[128][64] @0, Ks[64][64] @32768, Vs(e-major)[64][64] @49152, Ps[128][64] @65536
__global__ __launch_bounds__(256) void flash_tf32(const float* __restrict__ Qg,
                                                  const float* __restrict__ Kg,
                                                  const float* __restrict__ Vg,
                                                  float* __restrict__ Og) {
    extern __shared__ char smem[];
    const uint32_t QO = 0, KO = 32768, VO = 49152, PO = 65536;
    const int tid = threadIdx.x, lane = tid & 31, w = tid >> 5;
    const int qb = blockIdx.x, bh = blockIdx.y;
    const int b = bh >> 3, h = bh & 7;
    const size_t base = (size_t)b * SEQ * DM + (size_t)h * HD;
    const uint32_t sbase = (uint32_t)__cvta_generic_to_shared(smem);

    const int lr0 = tid >> 4;     // 0..15
    const int lchunk = tid & 15;  // 16B chunk within 256B row

    // load Q tile, pre-scaled by 1/sqrt(64), convert to tf32
#pragma unroll
    for (int l = 0; l < 8; l++) {
        int row = lr0 + l * 16;
        float4 v = *(const float4*)(Qg + base + (size_t)(qb * 128 + row) * DM + lchunk * 4);
        uint4 t;
        t.x = f2tf32(v.x * 0.125f);
        t.y = f2tf32(v.y * 0.125f);
        t.z = f2tf32(v.z * 0.125f);
        t.w = f2tf32(v.w * 0.125f);
        *(uint4*)(smem + QO + row * 256 + ((lchunk * 16) ^ ((row & 7) << 4))) = t;
    }

    float m0 = -1e30f, m1 = -1e30f, l0 = 0.f, l1 = 0.f;
    float o[8][4];
#pragma unroll
    for (int nt = 0; nt < 8; nt++)
#pragma unroll
        for (int i = 0; i < 4; i++) o[nt][i] = 0.f;

    const int strip = w * 16;
    const int arow = strip + (lane & 7) + ((lane >> 3) & 1) * 8;

    for (int kt = 0; kt < 16; kt++) {
        __syncthreads();  // previous tile's Ks/Vs reads complete
        // load K tile (j-major) and V tile (transposed to e-major), cvt to tf32
#pragma unroll
        for (int l = 0; l < 4; l++) {
            int row = lr0 + l * 16;
            float4 v = *(const float4*)(Kg + base + (size_t)(kt * 64 + row) * DM + lchunk * 4);
            uint4 t;
            t.x = f2tf32(v.x); t.y = f2tf32(v.y); t.z = f2tf32(v.z); t.w = f2tf32(v.w);
            *(uint4*)(smem + KO + row * 256 + ((lchunk * 16) ^ ((row & 7) << 4))) = t;

            float4 u = *(const float4*)(Vg + base + (size_t)(kt * 64 + row) * DM + lchunk * 4);
            uint32_t vals[4] = {f2tf32(u.x), f2tf32(u.y), f2tf32(u.z), f2tf32(u.w)};
#pragma unroll
            for (int i = 0; i < 4; i++) {
                int er = lchunk * 4 + i;  // e index
                *(uint32_t*)(smem + VO + er * 256 + ((row * 4) ^ ((er & 7) << 4))) = vals[i];
            }
        }
        __syncthreads();

        // S = Q @ K^T
        float s[8][4];
#pragma unroll
        for (int nt = 0; nt < 8; nt++)
#pragma unroll
            for (int i = 0; i < 4; i++) s[nt][i] = 0.f;
#pragma unroll
        for (int ks = 0; ks < 8; ks++) {
            uint32_t qa[4];
            ldsm4(qa, sbase + QO + arow * 256 +
                      ((ks * 32 + (lane & 16)) ^ ((arow & 7) << 4)));
#pragma unroll
            for (int p = 0; p < 4; p++) {
                int brow = p * 16 + (lane & 7) + ((lane >> 4) & 1) * 8;
                uint32_t kb4[4];
                ldsm4(kb4, sbase + KO + brow * 256 +
                          ((ks * 32 + ((lane & 8) << 1)) ^ ((brow & 7) << 4)));
                mma8(s[p * 2], qa, kb4[0], kb4[1]);
                mma8(s[p * 2 + 1], qa, kb4[2], kb4[3]);
            }
        }

        // online softmax (thread rows: r0 = strip+lane/4, r1 = r0+8)
        float mx0 = -1e30f, mx1 = -1e30f;
#pragma unroll
        for (int nt = 0; nt < 8; nt++) {
            mx0 = fmaxf(mx0, fmaxf(s[nt][0], s[nt][1]));
            mx1 = fmaxf(mx1, fmaxf(s[nt][2], s[nt][3]));
        }
        mx0 = fmaxf(mx0, __shfl_xor_sync(0xffffffffu, mx0, 1));
        mx0 = fmaxf(mx0, __shfl_xor_sync(0xffffffffu, mx0, 2));
        mx1 = fmaxf(mx1, __shfl_xor_sync(0xffffffffu, mx1, 1));
        mx1 = fmaxf(mx1, __shfl_xor_sync(0xffffffffu, mx1, 2));
        float mn0 = fmaxf(m0, mx0), mn1 = fmaxf(m1, mx1);
        float corr0 = __expf(m0 - mn0), corr1 = __expf(m1 - mn1);
        m0 = mn0; m1 = mn1;

        float sum0 = 0.f, sum1 = 0.f;
        const int prow0 = strip + (lane >> 2);
        const int prow1 = prow0 + 8;
#pragma unroll
        for (int nt = 0; nt < 8; nt++) {
            float p00 = __expf(s[nt][0] - m0), p01 = __expf(s[nt][1] - m0);
            float p10 = __expf(s[nt][2] - m1), p11 = __expf(s[nt][3] - m1);
            sum0 += p00 + p01;
            sum1 += p10 + p11;
            o[nt][0] *= corr0; o[nt][1] *= corr0;
            o[nt][2] *= corr1; o[nt][3] *= corr1;
            int cb = nt * 32 + (lane & 3) * 8;
            uint2 t0 = make_uint2(f2tf32(p00), f2tf32(p01));
            uint2 t1 = make_uint2(f2tf32(p10), f2tf32(p11));
            *(uint2*)(smem + PO + prow0 * 256 + (cb ^ ((prow0 & 7) << 4))) = t0;
            *(uint2*)(smem + PO + prow1 * 256 + (cb ^ ((prow1 & 7) << 4))) = t1;
        }
        sum0 += __shfl_xor_sync(0xffffffffu, sum0, 1);
        sum0 += __shfl_xor_sync(0xffffffffu, sum0, 2);
        sum1 += __shfl_xor_sync(0xffffffffu, sum1, 1);
        sum1 += __shfl_xor_sync(0xffffffffu, sum1, 2);
        l0 = l0 * corr0 + sum0;
        l1 = l1 * corr1 + sum1;
        __syncwarp();  // own-strip P stores visible to own-warp ldmatrix

        // O += P @ V
#pragma unroll
        for (int ks = 0; ks < 8; ks++) {
            uint32_t pa[4];
            ldsm4(pa, sbase + PO + arow * 256 +
                      ((ks * 32 + (lane & 16)) ^ ((arow & 7) << 4)));
#pragma unroll
            for (int p = 0; p < 4; p++) {
                int brow = p * 16 + (lane & 7) + ((lane >> 4) & 1) * 8;
                uint32_t vb[4];
                ldsm4(vb, sbase + VO + brow * 256 +
                          ((ks * 32 + ((lane & 8) << 1)) ^ ((brow & 7) << 4)));
                mma8(o[p * 2], pa, vb[0], vb[1]);
                mma8(o[p * 2 + 1], pa, vb[2], vb[3]);
            }
        }
    }

    // normalize + store (layout (b,n,h,e))
    float i0 = 1.f / l0, i1 = 1.f / l1;
    int row = qb * 128 + strip + (lane >> 2);
#pragma unroll
    for (int nt = 0; nt < 8; nt++) {
        int col = nt * 8 + (lane & 3) * 2;
        *(float2*)(Og + base + (size_t)row * DM + col) =
            make_float2(o[nt][0] * i0, o[nt][1] * i0);
        *(float2*)(Og + base + (size_t)(row + 8) * DM + col) =
            make_float2(o[nt][2] * i1, o[nt][3] * i1);
    }
}

extern "C" void kernel_launch(void* const* d_in, const int* in_sizes, int n_in,
                              void* d_out, int out_size) {
    const float* x   = (const float*)d_in[0];
    const float* r   = (const float*)d_in[1];
    const float* x_q = (const float*)d_in[2];
    const float* Wq  = (const float*)d_in[3];
    const float* Wk  = (const float*)d_in[4];
    const float* Wv  = (const float*)d_in[5];
    const float* Wo  = (const float*)d_in[6];
    float* out = (float*)d_out;

    float *pq, *pk, *pv, *po;
    cudaGetSymbolAddress((void**)&pq, g_q);
    cudaGetSymbolAddress((void**)&pk, g_k);
    cudaGetSymbolAddress((void**)&pv, g_v);
    cudaGetSymbolAddress((void**)&po, g_o);

    cudaFuncSetAttribute(gemm_tf32, cudaFuncAttributeMaxDynamicSharedMemorySize, 65536);
    cudaFuncSetAttribute(flash_tf32, cudaFuncAttributeMaxDynamicSharedMemorySize, 98304);

    dim3 ggrid(4, 128);
    // V projected BEFORE attention (linear: attn @ r @ Wv^T == attn @ (r @ Wv^T))
    gemm_tf32<<<ggrid, 256, 65536>>>(x_q, Wq, pq);
    gemm_tf32<<<ggrid, 256, 65536>>>(x,   Wk, pk);
    gemm_tf32<<<ggrid, 256, 65536>>>(r,   Wv, pv);

    dim3 fgrid(8, 128);
    flash_tf32<<<fgrid, 256, 98304>>>(pq, pk, pv, po);

    gemm_tf32<<<ggrid, 256, 65536>>>(po, Wo, out);
}

// round 3
// speedup vs baseline: 5.5124x; 1.5803x over previous
#include <cuda_runtime.h>
#include <cuda_fp16.h>
#include <stdint.h>

#define SEQ    1024
#define DM     512
#define MROWS  16384

// fp16 scratch: projected Q/K/V (layout (b,n,h,e)) and attention output.
__device__ __half g_q[MROWS * DM];
__device__ __half g_k[MROWS * DM];
__device__ __half g_v[MROWS * DM];
__device__ __half g_o[MROWS * DM];

// ---------------- PTX helpers ----------------
__device__ __forceinline__ uint32_t packh2(float a, float b) {
    __half2 h = __floats2half2_rn(a, b);
    return *(uint32_t*)&h;
}

__device__ __forceinline__ void ldsm4(uint32_t r[4], uint32_t addr) {
    asm volatile("ldmatrix.sync.aligned.m8n8.x4.shared.b16 {%0,%1,%2,%3}, [%4];"
                 : "=r"(r[0]), "=r"(r[1]), "=r"(r[2]), "=r"(r[3]) : "r"(addr));
}
__device__ __forceinline__ void ldsm4t(uint32_t r[4], uint32_t addr) {
    asm volatile("ldmatrix.sync.aligned.m8n8.x4.trans.shared.b16 {%0,%1,%2,%3}, [%4];"
                 : "=r"(r[0]), "=r"(r[1]), "=r"(r[2]), "=r"(r[3]) : "r"(addr));
}

__device__ __forceinline__ void mma16(float c[4], const uint32_t a[4],
                                      uint32_t b0, uint32_t b1) {
    asm volatile(
        "mma.sync.aligned.m16n8k16.row.col.f32.f16.f16.f32 "
        "{%0,%1,%2,%3},{%4,%5,%6,%7},{%8,%9},{%0,%1,%2,%3};"
        : "+f"(c[0]), "+f"(c[1]), "+f"(c[2]), "+f"(c[3])
        : "r"(a[0]), "r"(a[1]), "r"(a[2]), "r"(a[3]), "r"(b0), "r"(b1));
}

__device__ __forceinline__ void cpasync16(uint32_t dst, const void* src) {
    asm volatile("cp.async.cg.shared.global [%0], [%1], 16;" :: "r"(dst), "l"(src));
}
__device__ __forceinline__ void cpcommit() { asm volatile("cp.async.commit_group;"); }
template <int N>
__device__ __forceinline__ void cpwait() { asm volatile("cp.async.wait_group %0;" :: "n"(N)); }

__device__ __forceinline__ uint4 pack8(float4 a, float4 b) {
    return make_uint4(packh2(a.x, a.y), packh2(a.z, a.w),
                      packh2(b.x, b.y), packh2(b.z, b.w));
}

// ---------------- GEMM: C[M,512] = alpha * A[M,512] @ W[512,512]^T --------------
// fp16 mma m16n8k16, fp32 accumulate. 128x128 tile, BK=32, 8 warps (4m x 2n).
// smem: A-tile 128 rows stride 80B @0, W-tile @10240. (padded stride -> conflict-free ldsm)
template <typename AT, typename OT>
__global__ __launch_bounds__(256, 2) void gemm_h(const AT* __restrict__ A,
                                                 const float* __restrict__ W,
                                                 OT* __restrict__ C, float alpha) {
    __shared__ __align__(16) char smem[20480];
    const int tid = threadIdx.x, lane = tid & 31, w = tid >> 5;
    const int bm = blockIdx.y * 128, bn = blockIdx.x * 128;
    const int wm = (w & 3) * 32, wn = (w >> 2) * 64;
    const uint32_t sb = (uint32_t)__cvta_generic_to_shared(smem);

    float acc[2][8][4];
#pragma unroll
    for (int mt = 0; mt < 2; mt++)
#pragma unroll
        for (int nt = 0; nt < 8; nt++)
#pragma unroll
            for (int i = 0; i < 4; i++) acc[mt][nt][i] = 0.f;

    uint4 sA[2], sW[2];
    // load+convert staging for kb
    auto loadst = [&](int kb) {
#pragma unroll
        for (int i = 0; i < 2; i++) {
            int idx = tid + i * 256;
            int row = idx >> 2, ch = idx & 3;
            size_t offa = (size_t)(bm + row) * DM + kb * 32 + ch * 8;
            if constexpr (sizeof(AT) == 2) {
                sA[i] = *(const uint4*)(A + offa);
            } else {
                float4 a0 = *(const float4*)(A + offa);
                float4 a1 = *(const float4*)(A + offa + 4);
                sA[i] = pack8(a0, a1);
            }
            size_t offw = (size_t)(bn + row) * DM + kb * 32 + ch * 8;
            float4 w0 = *(const float4*)(W + offw);
            float4 w1 = *(const float4*)(W + offw + 4);
            sW[i] = pack8(w0, w1);
        }
    };

    loadst(0);
    for (int kb = 0; kb < 16; kb++) {
#pragma unroll
        for (int i = 0; i < 2; i++) {
            int idx = tid + i * 256;
            int row = idx >> 2, ch = idx & 3;
            uint32_t da = row * 80 + ch * 16;
            *(uint4*)(smem + da) = sA[i];
            *(uint4*)(smem + 10240 + da) = sW[i];
        }
        __syncthreads();
        if (kb < 15) loadst(kb + 1);
#pragma unroll
        for (int ks = 0; ks < 2; ks++) {
            uint32_t af[2][4];
#pragma unroll
            for (int mt = 0; mt < 2; mt++) {
                int row = wm + mt * 16 + (lane & 15);
                ldsm4(af[mt], sb + row * 80 + (2 * ks + (lane >> 4)) * 16);
            }
            uint32_t bf[4][4];
#pragma unroll
            for (int p = 0; p < 4; p++) {
                int row = wn + p * 16 + (lane & 7) + ((lane >> 3) & 1) * 8;
                ldsm4(bf[p], sb + 10240 + row * 80 + (2 * ks + (lane >> 4)) * 16);
            }
#pragma unroll
            for (int mt = 0; mt < 2; mt++)
#pragma unroll
                for (int p = 0; p < 4; p++) {
                    mma16(acc[mt][2 * p],     af[mt], bf[p][0], bf[p][2]);
                    mma16(acc[mt][2 * p + 1], af[mt], bf[p][1], bf[p][3]);
                }
        }
        __syncthreads();
    }

#pragma unroll
    for (int mt = 0; mt < 2; mt++)
#pragma unroll
        for (int nt = 0; nt < 8; nt++) {
            int row = bm + wm + mt * 16 + (lane >> 2);
            int col = bn + wn + nt * 8 + (lane & 3) * 2;
            float v0 = acc[mt][nt][0] * alpha, v1 = acc[mt][nt][1] * alpha;
            float v2 = acc[mt][nt][2] * alpha, v3 = acc[mt][nt][3] * alpha;
            if constexpr (sizeof(OT) == 2) {
                *(uint32_t*)((__half*)C + (size_t)row * DM + col) = packh2(v0, v1);
                *(uint32_t*)((__half*)C + (size_t)(row + 8) * DM + col) = packh2(v2, v3);
            } else {
                *(float2*)((float*)C + (size_t)row * DM + col) = make_float2(v0, v1);
                *(float2*)((float*)C + (size_t)(row + 8) * DM + col) = make_float2(v2, v3);
            }
        }
}

// ---------------- Flash attention (fp16 mma, fp32 accum) ----------------
// One (b,h) per blockIdx.y, 128 queries/block, 64-wide KV tiles, 8 warps.
// smem: Qs 128x128B @0; K/V double-buffered: stage s @16384+s*16384 (K 8K, V 8K).
__global__ __launch_bounds__(256, 2) void flash_h(const __half* __restrict__ Qg,
                                                  const __half* __restrict__ Kg,
                                                  const __half* __restrict__ Vg,
                                                  __half* __restrict__ Og) {
    extern __shared__ __align__(16) char smem[];
    const int tid = threadIdx.x, lane = tid & 31, w = tid >> 5;
    const int qb = blockIdx.x, bh = blockIdx.y;
    const int b = bh >> 3, h = bh & 7;
    const size_t base = (size_t)b * SEQ * DM + (size_t)h * 64;
    const uint32_t sb = (uint32_t)__cvta_generic_to_shared(smem);
    const int strip = w * 16;

    auto issue_tile = [&](int kt, int st) {
#pragma unroll
        for (int l = 0; l < 4; l++) {
            int idx = tid + l * 256;
            int t = idx >> 9;              // 0 = K, 1 = V
            int r = (idx >> 3) & 63;
            int ch = idx & 7;
            const __half* src = (t ? Vg : Kg) + base + (size_t)(kt * 64 + r) * DM + ch * 8;
            cpasync16(sb + 16384 + st * 16384 + t * 8192 + r * 128 +
                          ((ch * 16) ^ ((r & 7) << 4)),
                      src);
        }
    };

    // Q tile + KV tile 0 -> group 0
#pragma unroll
    for (int l = 0; l < 4; l++) {
        int idx = tid + l * 256;
        int row = idx >> 3, ch = idx & 7;
        cpasync16(sb + row * 128 + ((ch * 16) ^ ((row & 7) << 4)),
                  Qg + base + (size_t)(qb * 128 + row) * DM + ch * 8);
    }
    issue_tile(0, 0);
    cpcommit();

    float m0 = -1e30f, m1 = -1e30f, l0 = 0.f, l1 = 0.f;
    float o[8][4];
#pragma unroll
    for (int nt = 0; nt < 8; nt++)
#pragma unroll
        for (int i = 0; i < 4; i++) o[nt][i] = 0.f;
    uint32_t qa[4][4];

    for (int kt = 0; kt < 16; kt++) {
        if (kt < 15) {
            issue_tile(kt + 1, (kt + 1) & 1);
            cpcommit();
            cpwait<1>();
        } else {
            cpwait<0>();
        }
        __syncthreads();
        if (kt == 0) {
#pragma unroll
            for (int ks = 0; ks < 4; ks++) {
                int row = strip + (lane & 15);
                ldsm4(qa[ks], sb + row * 128 +
                              (((2 * ks + (lane >> 4)) * 16) ^ ((row & 7) << 4)));
            }
        }
        const uint32_t stK = sb + 16384 + (kt & 1) * 16384;
        const uint32_t stV = stK + 8192;

        // S = Q @ K^T
        float s[8][4];
#pragma unroll
        for (int nt = 0; nt < 8; nt++)
#pragma unroll
            for (int i = 0; i < 4; i++) s[nt][i] = 0.f;
#pragma unroll
        for (int ks = 0; ks < 4; ks++)
#pragma unroll
            for (int p = 0; p < 4; p++) {
                int row = p * 16 + (lane & 7) + ((lane >> 3) & 1) * 8;
                uint32_t kb4[4];
                ldsm4(kb4, stK + row * 128 +
                           (((2 * ks + (lane >> 4)) * 16) ^ ((row & 7) << 4)));
                mma16(s[2 * p],     qa[ks], kb4[0], kb4[2]);
                mma16(s[2 * p + 1], qa[ks], kb4[1], kb4[3]);
            }

        // online softmax (rows: g = strip+lane/4, g+8)
        float mx0 = -1e30f, mx1 = -1e30f;
#pragma unroll
        for (int nt = 0; nt < 8; nt++) {
            mx0 = fmaxf(mx0, fmaxf(s[nt][0], s[nt][1]));
            mx1 = fmaxf(mx1, fmaxf(s[nt][2], s[nt][3]));
        }
        mx0 = fmaxf(mx0, __shfl_xor_sync(0xffffffffu, mx0, 1));
        mx0 = fmaxf(mx0, __shfl_xor_sync(0xffffffffu, mx0, 2));
        mx1 = fmaxf(mx1, __shfl_xor_sync(0xffffffffu, mx1, 1));
        mx1 = fmaxf(mx1, __shfl_xor_sync(0xffffffffu, mx1, 2));
        float mn0 = fmaxf(m0, mx0), mn1 = fmaxf(m1, mx1);
        float c0 = __expf(m0 - mn0), c1 = __expf(m1 - mn1);
        m0 = mn0; m1 = mn1;

        float sum0 = 0.f, sum1 = 0.f;
        float pe[8][4];
#pragma unroll
        for (int nt = 0; nt < 8; nt++) {
            pe[nt][0] = __expf(s[nt][0] - m0);
            pe[nt][1] = __expf(s[nt][1] - m0);
            pe[nt][2] = __expf(s[nt][2] - m1);
            pe[nt][3] = __expf(s[nt][3] - m1);
            sum0 += pe[nt][0] + pe[nt][1];
            sum1 += pe[nt][2] + pe[nt][3];
            o[nt][0] *= c0; o[nt][1] *= c0;
            o[nt][2] *= c1; o[nt][3] *= c1;
        }
        sum0 += __shfl_xor_sync(0xffffffffu, sum0, 1);
        sum0 += __shfl_xor_sync(0xffffffffu, sum0, 2);
        sum1 += __shfl_xor_sync(0xffffffffu, sum1, 1);
        sum1 += __shfl_xor_sync(0xffffffffu, sum1, 2);
        l0 = l0 * c0 + sum0;
        l1 = l1 * c1 + sum1;

        // Pack P fragments directly into PV A-operands (no smem round-trip):
        // C-fragment of S has exactly the A-fragment layout of m16n8k16.
        uint32_t pa[4][4];
#pragma unroll
        for (int ks = 0; ks < 4; ks++) {
            pa[ks][0] = packh2(pe[2 * ks][0], pe[2 * ks][1]);
            pa[ks][1] = packh2(pe[2 * ks][2], pe[2 * ks][3]);
            pa[ks][2] = packh2(pe[2 * ks + 1][0], pe[2 * ks + 1][1]);
            pa[ks][3] = packh2(pe[2 * ks + 1][2], pe[2 * ks + 1][3]);
        }

        // O += P @ V  (V row-major in smem; ldmatrix.trans makes the col-B operand)
#pragma unroll
        for (int ks = 0; ks < 4; ks++)
#pragma unroll
            for (int p = 0; p < 4; p++) {
                int row = ks * 16 + (lane & 7) + ((lane >> 3) & 1) * 8;
                uint32_t vb[4];
                ldsm4t(vb, stV + row * 128 +
                           (((2 * p + (lane >> 4)) * 16) ^ ((row & 7) << 4)));
                mma16(o[2 * p],     pa[ks], vb[0], vb[1]);
                mma16(o[2 * p + 1], pa[ks], vb[2], vb[3]);
            }
        __syncthreads();
    }

    // normalize + store fp16 (layout (b,n,h,e))
    float i0 = 1.f / l0, i1 = 1.f / l1;
    int row = qb * 128 + strip + (lane >> 2);
#pragma unroll
    for (int nt = 0; nt < 8; nt++) {
        int col = nt * 8 + (lane & 3) * 2;
        *(uint32_t*)(Og + base + (size_t)row * DM + col) =
            packh2(o[nt][0] * i0, o[nt][1] * i0);
        *(uint32_t*)(Og + base + (size_t)(row + 8) * DM + col) =
            packh2(o[nt][2] * i1, o[nt][3] * i1);
    }
}

extern "C" void kernel_launch(void* const* d_in, const int* in_sizes, int n_in,
                              void* d_out, int out_size) {
    const float* x   = (const float*)d_in[0];
    const float* r   = (const float*)d_in[1];
    const float* x_q = (const float*)d_in[2];
    const float* Wq  = (const float*)d_in[3];
    const float* Wk  = (const float*)d_in[4];
    const float* Wv  = (const float*)d_in[5];
    const float* Wo  = (const float*)d_in[6];
    float* out = (float*)d_out;

    __half *pq, *pk, *pv, *po;
    cudaGetSymbolAddress((void**)&pq, g_q);
    cudaGetSymbolAddress((void**)&pk, g_k);
    cudaGetSymbolAddress((void**)&pv, g_v);
    cudaGetSymbolAddress((void**)&po, g_o);

    const int fsmem = 49152;
    cudaFuncSetAttribute(flash_h, cudaFuncAttributeMaxDynamicSharedMemorySize, fsmem);

    dim3 ggrid(4, 128);
    // Q projection carries the 1/sqrt(HD)=1/8 softmax scale.
    // V projected BEFORE attention (linear: attn @ r @ Wv^T == attn @ (r @ Wv^T)).
    gemm_h<float, __half><<<ggrid, 256>>>(x_q, Wq, pq, 0.125f);
    gemm_h<float, __half><<<ggrid, 256>>>(x,   Wk, pk, 1.0f);
    gemm_h<float, __half><<<ggrid, 256>>>(r,   Wv, pv, 1.0f);

    dim3 fgrid(8, 128);
    flash_h<<<fgrid, 256, fsmem>>>(pq, pk, pv, po);

    gemm_h<__half, float><<<ggrid, 256>>>(po, Wo, out, 1.0f);
}